// round 15
// baseline (speedup 1.0000x reference)
#include <cuda_runtime.h>
#include <cuda_fp16.h>
#include <cstdint>
#include <cstddef>

// ---------------------------------------------------------------------------
// Rel_Transformer_Layer: N=2048, D=1024, H=8, DK=128, L=4, FF=4096
// Round 15: R14 + half-packed GEMM hand-offs (flash->Wo, FFN1->FFN2) and
// half2 bias2d (halves flash bias stream). hgemm templated on A format.
// ---------------------------------------------------------------------------

#define NTOK 2048
#define DMOD 1024
#define HEADS 8
#define DKH 128
#define FFD 4096
#define SCALE 0.08838834764831845f

// -------------------- scratch ------------------
__device__ float g_x2[NTOK * DMOD];
__device__ uint32_t g_bias2dH[(size_t)NTOK * NTOK / 2];
__device__ float g_bqkv[3 * DMOD];
__device__ float g_qkv[3 * NTOK * DMOD];
__device__ uint32_t g_aoH[NTOK * DMOD / 2];
__device__ float g_h1[NTOK * DMOD];
__device__ uint32_t g_ffH[(size_t)NTOK * FFD / 2];
__device__ float g_part[(size_t)2 * NTOK * DMOD];
__device__ float g_etw[64];
__device__ uint32_t g_Wqp[512 * 3 * DMOD];     // [512][3072] packed half2
__device__ uint32_t g_Wop[512 * DMOD];
__device__ uint32_t g_W1p[512 * FFD];
__device__ uint32_t g_W2p[2048 * DMOD];
__device__ uint32_t g_Kp[HEADS * 64 * NTOK];   // [h][dk/2][tok]
__device__ uint32_t g_Vp[HEADS * 1024 * DKH];  // [h][tok/2][dk]

// -------------------- helpers ------------------
__device__ __forceinline__ uint32_t h2(float a, float b) {
    __half2 h = __floats2half2_rn(a, b);
    return *(uint32_t*)&h;
}
__device__ __forceinline__ void cpasync16(uint32_t s, const void* g) {
    asm volatile("cp.async.cg.shared.global [%0], [%1], 16;" :: "r"(s), "l"(g));
}
#define COMMIT() asm volatile("cp.async.commit_group;" ::: "memory")
#define WAITG1() asm volatile("cp.async.wait_group 1;" ::: "memory")

#define MMA_F16(acc, af, bf)                                               \
    asm volatile(                                                          \
        "mma.sync.aligned.m16n8k16.row.col.f32.f16.f16.f32 "               \
        "{%0,%1,%2,%3}, {%4,%5,%6,%7}, {%8,%9}, {%0,%1,%2,%3};"            \
        : "+f"(acc[0]), "+f"(acc[1]), "+f"(acc[2]), "+f"(acc[3])           \
        : "r"(af[0]), "r"(af[1]), "r"(af[2]), "r"(af[3]),                  \
          "r"(bf[0]), "r"(bf[1]))

#define AFW1H 2048
__device__ __forceinline__ void storeA_h(
    uint32_t* AFb, const float4 A0[2], const float4 A1[2],
    int wmS, int iS, int g, int tg)
{
#pragma unroll
    for (int ks = 0; ks < 2; ks++) {
        const float* f0 = (const float*)&A0[ks];
        const float* f1 = (const float*)&A1[ks];
#pragma unroll
        for (int pp = 0; pp < 2; pp++) {
            const int kp = 2 * tg + pp;
            const int tgp = kp & 3;
            const int hk = kp >> 2;
            const uint32_t w0 = h2(f0[2 * pp], f0[2 * pp + 1]);
            const uint32_t w1 = h2(f1[2 * pp], f1[2 * pp + 1]);
            const int idx = (((wmS * 2 + ks) * 4 + iS) * 32 +
                             ((g * 4 + tgp) ^ (g & 3))) * 4 + 2 * hk;
            *(uint2*)&AFb[idx] = make_uint2(w0, w1);
        }
    }
}

// pre-packed half2 A variant (no conversion)
__device__ __forceinline__ void storeA_pre(
    uint32_t* AFb, const uint2 U0[2], const uint2 U1[2],
    int wmS, int iS, int g, int tg)
{
#pragma unroll
    for (int ks = 0; ks < 2; ks++) {
#pragma unroll
        for (int pp = 0; pp < 2; pp++) {
            const int kp = 2 * tg + pp;
            const int tgp = kp & 3;
            const int hk = kp >> 2;
            const uint32_t w0 = pp ? U0[ks].y : U0[ks].x;
            const uint32_t w1 = pp ? U1[ks].y : U1[ks].x;
            const int idx = (((wmS * 2 + ks) * 4 + iS) * 32 +
                             ((g * 4 + tgp) ^ (g & 3))) * 4 + 2 * hk;
            *(uint2*)&AFb[idx] = make_uint2(w0, w1);
        }
    }
}

// 64-row variant (R13 verified)
__device__ __forceinline__ void storeA_h64(
    uint32_t* AFb, const float4 A0, const float4 A1,
    int wmS, int iS, int par, int g, int tg)
{
    const float4 A[2] = {A0, A1};
#pragma unroll
    for (int ks = 0; ks < 2; ks++) {
        const float* f = (const float*)&A[ks];
#pragma unroll
        for (int pp = 0; pp < 2; pp++) {
            const int kp = 2 * tg + pp;
            const int tgp = kp & 3;
            const int hk = kp >> 2;
            const uint32_t w = h2(f[2 * pp], f[2 * pp + 1]);
            const int idx = (((wmS * 2 + ks) * 2 + iS) * 32 +
                             ((g * 4 + tgp) ^ (g & 3))) * 4 + 2 * hk + par;
            AFb[idx] = w;
        }
    }
}

// ==================== fp16 GEMM, templated A format ====================
// AH=0: A fp32 [M][K]; AH=1: A packed half2 [M][K/2] words.
// CH != null: output packed half2 [M][N/2]. Else splitCols/fp32 (R14).
#define HPITCH 136
#define HBBW (16 * HPITCH)
#define HSMEM_BYTES ((2 * AFW1H + 3 * HBBW) * 4)

template<int AH>
__global__ __launch_bounds__(256, 2) void hgemm_t(
    const void* __restrict__ A, const uint32_t* __restrict__ Bp,
    const float* __restrict__ biasvec, float* __restrict__ C,
    uint32_t* __restrict__ CH,
    int M, int N, int K, size_t sC, int doRelu, int nsplit, int splitCols)
{
    extern __shared__ uint32_t sm[];
    uint32_t* AF = sm;
    uint32_t* BBuf = sm + 2 * AFW1H;

    const int tid = threadIdx.x, wid = tid >> 5, lane = tid & 31;
    const int g = lane >> 2, tg = lane & 3, wm = wid >> 2, wn = wid & 3;
    const int split = blockIdx.z % nsplit;
    const int Keff = K / nsplit, nIter = Keff / 32;

    const uint32_t* Bb = Bp + (size_t)(split * Keff / 2) * N
                        + (size_t)blockIdx.x * 128;
    const float* bvv = biasvec;

    const int wmS = wid >> 2, iS = wid & 3;
    // A staging pointers
    const float* Ag0 = nullptr; const float* Ag1 = nullptr;
    const uint32_t* Ag0h = nullptr; const uint32_t* Ag1h = nullptr;
    if (AH) {
        const uint32_t* Ab = (const uint32_t*)A + (size_t)split * (Keff >> 1)
                           + (size_t)blockIdx.y * 128 * (K >> 1);
        Ag0h = Ab + (size_t)(wid * 16 + g) * (K >> 1) + tg * 2;
        Ag1h = Ag0h + (size_t)8 * (K >> 1);
    } else {
        const float* Ab = (const float*)A + (size_t)split * Keff
                        + (size_t)blockIdx.y * 128 * K;
        Ag0 = Ab + (size_t)(wid * 16 + g) * K + tg * 4;
        Ag1 = Ag0 + (size_t)8 * K;
    }

    const int bRow = tid >> 5;
    const int bCol = (tid & 31) << 2;
    const uint32_t* Bg = Bb + (size_t)bRow * N + bCol;
    const uint32_t bSh = (uint32_t)__cvta_generic_to_shared(BBuf);

    float4 A0[2], A1[2];
    uint2 U0[2], U1[2];
    // stage tile 0
    if (AH) {
        U0[0] = *(const uint2*)(Ag0h);      U0[1] = *(const uint2*)(Ag0h + 8);
        U1[0] = *(const uint2*)(Ag1h);      U1[1] = *(const uint2*)(Ag1h + 8);
        storeA_pre(AF, U0, U1, wmS, iS, g, tg);
    } else {
        A0[0] = *(const float4*)(Ag0);      A0[1] = *(const float4*)(Ag0 + 16);
        A1[0] = *(const float4*)(Ag1);      A1[1] = *(const float4*)(Ag1 + 16);
        storeA_h(AF, A0, A1, wmS, iS, g, tg);
    }
#pragma unroll
    for (int rh = 0; rh < 16; rh += 8)
        cpasync16(bSh + (((bRow + rh) * HPITCH + bCol) << 2), Bg + (size_t)rh * N);
    COMMIT();
    // stage tile 1
    if (AH) {
        U0[0] = *(const uint2*)(Ag0h + 16); U0[1] = *(const uint2*)(Ag0h + 24);
        U1[0] = *(const uint2*)(Ag1h + 16); U1[1] = *(const uint2*)(Ag1h + 24);
    } else {
        A0[0] = *(const float4*)(Ag0 + 32); A0[1] = *(const float4*)(Ag0 + 48);
        A1[0] = *(const float4*)(Ag1 + 32); A1[1] = *(const float4*)(Ag1 + 48);
    }
    {
        const uint32_t* Bn = Bg + (size_t)16 * N;
        const uint32_t db = bSh + (HBBW << 2);
#pragma unroll
        for (int rh = 0; rh < 16; rh += 8)
            cpasync16(db + (((bRow + rh) * HPITCH + bCol) << 2), Bn + (size_t)rh * N);
    }
    COMMIT();

    float acc[4][4][4];
#pragma unroll
    for (int i = 0; i < 4; i++)
#pragma unroll
        for (int j = 0; j < 4; j++)
#pragma unroll
            for (int r = 0; r < 4; r++) acc[i][j][r] = 0.f;

    for (int it = 0; it < nIter; it++) {
        WAITG1();
        __syncthreads();
        if (it + 2 < nIter) {
            const uint32_t* Bn = Bg + (size_t)(it + 2) * 16 * N;
            const uint32_t db = bSh + (((it + 2) % 3) * HBBW << 2);
#pragma unroll
            for (int rh = 0; rh < 16; rh += 8)
                cpasync16(db + (((bRow + rh) * HPITCH + bCol) << 2), Bn + (size_t)rh * N);
        }
        COMMIT();
        if (it + 1 < nIter) {
            uint32_t* AFb = AF + ((it + 1) & 1) * AFW1H;
            if (AH) storeA_pre(AFb, U0, U1, wmS, iS, g, tg);
            else    storeA_h(AFb, A0, A1, wmS, iS, g, tg);
        }
        if (it + 2 < nIter) {
            if (AH) {
                const uint32_t* An0 = Ag0h + (size_t)(it + 2) * 16;
                const uint32_t* An1 = Ag1h + (size_t)(it + 2) * 16;
                U0[0] = *(const uint2*)(An0); U0[1] = *(const uint2*)(An0 + 8);
                U1[0] = *(const uint2*)(An1); U1[1] = *(const uint2*)(An1 + 8);
            } else {
                const float* An0 = Ag0 + (size_t)(it + 2) * 32;
                const float* An1 = Ag1 + (size_t)(it + 2) * 32;
                A0[0] = *(const float4*)(An0); A0[1] = *(const float4*)(An0 + 16);
                A1[0] = *(const float4*)(An1); A1[1] = *(const float4*)(An1 + 16);
            }
        }
        const uint32_t* AFr = AF + (it & 1) * AFW1H;
        const uint32_t* Bs = BBuf + (it % 3) * HBBW;
#pragma unroll
        for (int ks = 0; ks < 2; ks++) {
            uint32_t af[4][4], bf[4][2];
#pragma unroll
            for (int i = 0; i < 4; i++) {
                const uint4 qd = *(const uint4*)
                    &AFr[(((wm * 2 + ks) * 4 + i) * 32 + (lane ^ (g & 3))) * 4];
                af[i][0] = qd.x; af[i][1] = qd.y; af[i][2] = qd.z; af[i][3] = qd.w;
            }
            const int kl = ks * 8 + tg;
#pragma unroll
            for (int j = 0; j < 4; j++) {
                const int c0 = wn * 32 + j * 8 + g;
                bf[j][0] = Bs[kl * HPITCH + c0];
                bf[j][1] = Bs[(kl + 4) * HPITCH + c0];
            }
#pragma unroll
            for (int i = 0; i < 4; i++)
#pragma unroll
                for (int j = 0; j < 4; j++) MMA_F16(acc[i][j], af[i], bf[j]);
        }
        __syncthreads();
    }

#pragma unroll
    for (int i = 0; i < 4; i++) {
        const int row = blockIdx.y * 128 + wm * 64 + i * 16 + g;
#pragma unroll
        for (int j = 0; j < 4; j++) {
            const int col = blockIdx.x * 128 + wn * 32 + j * 8 + 2 * tg;
            float v0 = acc[i][j][0], v1 = acc[i][j][1];
            float v2 = acc[i][j][2], v3 = acc[i][j][3];
            if (bvv) {
                v0 += bvv[col]; v1 += bvv[col + 1];
                v2 += bvv[col]; v3 += bvv[col + 1];
            }
            if (doRelu) {
                v0 = fmaxf(v0, 0.f); v1 = fmaxf(v1, 0.f);
                v2 = fmaxf(v2, 0.f); v3 = fmaxf(v3, 0.f);
            }
            if (CH) {
                CH[(size_t)row * (N >> 1) + (col >> 1)] = h2(v0, v1);
                CH[(size_t)(row + 8) * (N >> 1) + (col >> 1)] = h2(v2, v3);
            } else if (splitCols) {
                const int cb = col / splitCols;
                float* Cw = C + (size_t)cb * sC + (size_t)row * splitCols
                          + (col - cb * splitCols);
                *(float2*)(Cw) = make_float2(v0, v1);
                *(float2*)(Cw + (size_t)8 * splitCols) = make_float2(v2, v3);
            } else {
                float* Cw = C + (size_t)blockIdx.z * sC + (size_t)row * N + col;
                *(float2*)(Cw) = make_float2(v0, v1);
                *(float2*)(Cw + (size_t)8 * N) = make_float2(v2, v3);
            }
        }
    }
}

// ==================== fp16 flash, 64-row blocks, occ 2 ====================
#define FBBW (32 * HPITCH)
#define PSP 68
#define F6_BB  4096
#define F6_PS  (F6_BB + 3 * FBBW)
#define F6_RED (F6_PS + 64 * PSP)
#define FLASH_SMEM ((F6_RED + 512) * 4)

__global__ __launch_bounds__(256, 2) void flash_h(
    const float* __restrict__ Q, const uint32_t* __restrict__ Kp,
    const uint32_t* __restrict__ Vp, const uint32_t* __restrict__ bias2dH,
    uint32_t* __restrict__ OH)
{
    extern __shared__ uint32_t sm[];
    uint32_t* AFQ = sm;
    uint32_t* BBuf = sm + F6_BB;
    uint32_t* Ps = sm + F6_PS;
    float* redM = (float*)(sm + F6_RED);
    float* redS = redM + 256;

    const int tid = threadIdx.x, wid = tid >> 5, lane = tid & 31;
    const int g = lane >> 2, tg = lane & 3, wm = wid >> 2, wn = wid & 3;
    const int h = blockIdx.z, by = blockIdx.y;

    const float* Qh = Q + (size_t)h * 256 * DMOD;
    const uint32_t* Kh = Kp + (size_t)h * 64 * NTOK;
    const uint32_t* Vh = Vp + (size_t)h * 1024 * DKH;

    const int bRow = tid >> 5, bCol = (tid & 31) << 2;
    const uint32_t bSh = (uint32_t)__cvta_generic_to_shared(BBuf);
    auto issue_body = [&](int qq) {
        const int t = qq >> 2, ph = qq & 3;
        const uint32_t* src;
        int stride;
        if (ph < 2) { src = Kh + (size_t)(ph * 32 + bRow) * NTOK + t * 128 + bCol; stride = NTOK; }
        else        { src = Vh + (size_t)(t * 64 + (ph - 2) * 32 + bRow) * DKH + bCol; stride = DKH; }
        const uint32_t db = bSh + ((qq % 3) * FBBW << 2);
#pragma unroll
        for (int rh = 0; rh < 32; rh += 8)
            cpasync16(db + (((bRow + rh) * HPITCH + bCol) << 2), src + (size_t)rh * stride);
    };
    issue_body(0); COMMIT();
    issue_body(1); COMMIT();

    {
        const int blk = wid >> 1, par = wid & 1;
        const int wmS = blk >> 1, iS = blk & 1;
        const float* Qg = Qh + (size_t)(by * 64 + wid * 8 + g) * DKH + tg * 4;
#pragma unroll
        for (int c = 0; c < 4; c++) {
            const float4 A0 = *(const float4*)(Qg + c * 32);
            const float4 A1 = *(const float4*)(Qg + c * 32 + 16);
            storeA_h64(AFQ + c * 1024, A0, A1, wmS, iS, par, g, tg);
        }
    }

    float m4[4], l4[4], oacc[2][4][4];
#pragma unroll
    for (int s = 0; s < 4; s++) { m4[s] = -1e30f; l4[s] = 0.f; }
#pragma unroll
    for (int i = 0; i < 2; i++)
#pragma unroll
        for (int j = 0; j < 4; j++)
#pragma unroll
            for (int r = 0; r < 4; r++) oacc[i][j][r] = 0.f;

    int q = 0;
    for (int t = 0; t < 16; t++) {
        float sacc[2][4][4];
#pragma unroll
        for (int i = 0; i < 2; i++)
#pragma unroll
            for (int j = 0; j < 4; j++)
#pragma unroll
                for (int r = 0; r < 4; r++) sacc[i][j][r] = 0.f;

        for (int c = 0; c < 2; c++, q++) {
            WAITG1();
            __syncthreads();
            if (q + 2 < 64) issue_body(q + 2);
            COMMIT();
            const uint32_t* Bs = BBuf + (q % 3) * FBBW;
#pragma unroll
            for (int ks4 = 0; ks4 < 4; ks4++) {
                const uint32_t* AFr = AFQ + (c * 2 + (ks4 >> 1)) * 1024;
                const int ks = ks4 & 1;
                uint32_t af[2][4], bf[4][2];
#pragma unroll
                for (int i = 0; i < 2; i++) {
                    const uint4 qd = *(const uint4*)
                        &AFr[(((wm * 2 + ks) * 2 + i) * 32 + (lane ^ (g & 3))) * 4];
                    af[i][0] = qd.x; af[i][1] = qd.y; af[i][2] = qd.z; af[i][3] = qd.w;
                }
                const int kl = ks4 * 8 + tg;
#pragma unroll
                for (int j = 0; j < 4; j++) {
                    const int c0 = wn * 32 + j * 8 + g;
                    bf[j][0] = Bs[kl * HPITCH + c0];
                    bf[j][1] = Bs[(kl + 4) * HPITCH + c0];
                }
#pragma unroll
                for (int i = 0; i < 2; i++)
#pragma unroll
                    for (int j = 0; j < 4; j++) MMA_F16(sacc[i][j], af[i], bf[j]);
            }
            __syncthreads();
        }

#pragma unroll
        for (int i = 0; i < 2; i++) {
            const int rg = by * 64 + wm * 32 + i * 16 + g;
#pragma unroll
            for (int j = 0; j < 4; j++) {
                const int cg = t * 128 + wn * 32 + j * 8 + 2 * tg;
                const uint32_t bw0 = bias2dH[((size_t)rg * NTOK + cg) >> 1];
                const uint32_t bw1 = bias2dH[((size_t)(rg + 8) * NTOK + cg) >> 1];
                const float2 b0 = __half22float2(*(const __half2*)&bw0);
                const float2 b1 = __half22float2(*(const __half2*)&bw1);
                sacc[i][j][0] = sacc[i][j][0] * SCALE + b0.x;
                sacc[i][j][1] = sacc[i][j][1] * SCALE + b0.y;
                sacc[i][j][2] = sacc[i][j][2] * SCALE + b1.x;
                sacc[i][j][3] = sacc[i][j][3] * SCALE + b1.y;
            }
        }

        float pm[4];
#pragma unroll
        for (int i = 0; i < 2; i++)
#pragma unroll
            for (int h2i = 0; h2i < 2; h2i++) {
                float v = -1e30f;
#pragma unroll
                for (int j = 0; j < 4; j++)
                    v = fmaxf(v, fmaxf(sacc[i][j][2 * h2i], sacc[i][j][2 * h2i + 1]));
                pm[i * 2 + h2i] = v;
            }
#pragma unroll
        for (int s = 0; s < 4; s++) {
            pm[s] = fmaxf(pm[s], __shfl_xor_sync(~0u, pm[s], 1));
            pm[s] = fmaxf(pm[s], __shfl_xor_sync(~0u, pm[s], 2));
        }
#pragma unroll
        for (int s = 0; s < 4; s++) {
            const int row = wm * 32 + (s >> 1) * 16 + (s & 1) * 8 + g;
            if (tg == 0) redM[row * 4 + wn] = pm[s];
        }
        __syncthreads();

        float alpha[4], nm[4];
#pragma unroll
        for (int s = 0; s < 4; s++) {
            const int row = wm * 32 + (s >> 1) * 16 + (s & 1) * 8 + g;
            float tm = fmaxf(fmaxf(redM[row * 4], redM[row * 4 + 1]),
                             fmaxf(redM[row * 4 + 2], redM[row * 4 + 3]));
            nm[s] = fmaxf(m4[s], tm);
            alpha[s] = __expf(m4[s] - nm[s]);
            m4[s] = nm[s];
        }

        float ps[4];
#pragma unroll
        for (int s = 0; s < 4; s++) ps[s] = 0.f;
#pragma unroll
        for (int i = 0; i < 2; i++)
#pragma unroll
            for (int h2i = 0; h2i < 2; h2i++) {
                const int row = wm * 32 + i * 16 + h2i * 8 + g;
#pragma unroll
                for (int j = 0; j < 4; j++) {
                    const int cw = wn * 16 + j * 4 + tg;
                    float p0 = __expf(sacc[i][j][2 * h2i] - nm[i * 2 + h2i]);
                    float p1 = __expf(sacc[i][j][2 * h2i + 1] - nm[i * 2 + h2i]);
                    ps[i * 2 + h2i] += p0 + p1;
                    Ps[row * PSP + cw] = h2(p0, p1);
                }
            }
#pragma unroll
        for (int s = 0; s < 4; s++) {
            ps[s] += __shfl_xor_sync(~0u, ps[s], 1);
            ps[s] += __shfl_xor_sync(~0u, ps[s], 2);
            const int row = wm * 32 + (s >> 1) * 16 + (s & 1) * 8 + g;
            if (tg == 0) redS[row * 4 + wn] = ps[s];
        }
        __syncthreads();
#pragma unroll
        for (int s = 0; s < 4; s++) {
            const int row = wm * 32 + (s >> 1) * 16 + (s & 1) * 8 + g;
            const float ts = redS[row * 4] + redS[row * 4 + 1] +
                             redS[row * 4 + 2] + redS[row * 4 + 3];
            l4[s] = alpha[s] * l4[s] + ts;
        }
#pragma unroll
        for (int i = 0; i < 2; i++)
#pragma unroll
            for (int j = 0; j < 4; j++) {
                oacc[i][j][0] *= alpha[i * 2];
                oacc[i][j][1] *= alpha[i * 2];
                oacc[i][j][2] *= alpha[i * 2 + 1];
                oacc[i][j][3] *= alpha[i * 2 + 1];
            }

        for (int c = 0; c < 2; c++, q++) {
            WAITG1();
            __syncthreads();
            if (q + 2 < 64) issue_body(q + 2);
            COMMIT();
            const uint32_t* Bs = BBuf + (q % 3) * FBBW;
#pragma unroll
            for (int ks4 = 0; ks4 < 4; ks4++) {
                uint32_t af[2][4], bf[4][2];
                const int kk = c * 32 + ks4 * 8 + tg;
#pragma unroll
                for (int i = 0; i < 2; i++) {
                    const int r0 = wm * 32 + i * 16 + g;
                    af[i][0] = Ps[r0 * PSP + kk];
                    af[i][1] = Ps[(r0 + 8) * PSP + kk];
                    af[i][2] = Ps[r0 * PSP + kk + 4];
                    af[i][3] = Ps[(r0 + 8) * PSP + kk + 4];
                }
                const int kl = ks4 * 8 + tg;
#pragma unroll
                for (int j = 0; j < 4; j++) {
                    const int c0 = wn * 32 + j * 8 + g;
                    bf[j][0] = Bs[kl * HPITCH + c0];
                    bf[j][1] = Bs[(kl + 4) * HPITCH + c0];
                }
#pragma unroll
                for (int i = 0; i < 2; i++)
#pragma unroll
                    for (int j = 0; j < 4; j++) MMA_F16(oacc[i][j], af[i], bf[j]);
            }
            __syncthreads();
        }
    }

    // epilogue: write packed half2 (pairs along dk = Wo's K)
    uint32_t* OhH = OH + (((size_t)h * 256 * DMOD) >> 1);
#pragma unroll
    for (int i = 0; i < 2; i++) {
        const int row = by * 64 + wm * 32 + i * 16 + g;
        const float inv0 = 1.f / l4[i * 2];
        const float inv1 = 1.f / l4[i * 2 + 1];
#pragma unroll
        for (int j = 0; j < 4; j++) {
            const int col = wn * 32 + j * 8 + 2 * tg;
            OhH[((size_t)row * DKH + col) >> 1] =
                h2(oacc[i][j][0] * inv0, oacc[i][j][1] * inv0);
            OhH[((size_t)(row + 8) * DKH + col) >> 1] =
                h2(oacc[i][j][2] * inv1, oacc[i][j][3] * inv1);
        }
    }
}

// ---- weight pack ----
__global__ void packW_k(const float* __restrict__ W, uint32_t* __restrict__ Wp,
                        int N, int NS, int off)
{
    const size_t i = (size_t)blockIdx.x * 256 + threadIdx.x;
    const size_t k2 = i / N, n = i - k2 * N;
    Wp[k2 * NS + off + n] = h2(W[2 * k2 * N + n], W[(2 * k2 + 1) * N + n]);
}

// ---- K/V repack (from fp32 qkv regions) ----
__global__ void packKV_k(const float* __restrict__ qkv,
                         uint32_t* __restrict__ Kp, uint32_t* __restrict__ Vp)
{
    const size_t i = (size_t)blockIdx.x * 256 + threadIdx.x;
    const size_t ND = (size_t)NTOK * DMOD;
    if (blockIdx.z == 0) {
        const int hh = (int)(i >> 17);
        const size_t r = i & 131071;
        const size_t d2 = r >> 11, tk = r & 2047;
        const float* base = qkv + ND + (size_t)hh * 256 * DMOD;
        Kp[i] = h2(base[2 * d2 * 2048 + tk], base[(2 * d2 + 1) * 2048 + tk]);
    } else {
        const int hh = (int)(i >> 17);
        const size_t r = i & 131071;
        const size_t t2 = r >> 7, d = r & 127;
        const float* base = qkv + 2 * ND + (size_t)hh * 256 * DMOD;
        Vp[i] = h2(base[2 * t2 * 128 + d], base[(2 * t2 + 1) * 128 + d]);
    }
}

// ---- fused: y = LayerNorm(resid + part0 + part1 + bias) * g + b ----
__global__ void red_ln_k(const float* __restrict__ part,
                         const float* __restrict__ bias,
                         const float* __restrict__ resid,
                         const float* __restrict__ g, const float* __restrict__ b,
                         float* __restrict__ y)
{
    const int n = blockIdx.x;
    const size_t ND = (size_t)NTOK * DMOD;
    const float4* p0 = (const float4*)(part + (size_t)n * DMOD);
    const float4* p1 = (const float4*)(part + ND + (size_t)n * DMOD);
    const float4* br = (const float4*)bias;
    const float4* rr = (const float4*)(resid + (size_t)n * DMOD);
    const int i = threadIdx.x;
    float4 a = p0[i], c = p1[i], bb = br[i], r = rr[i];
    float v0 = r.x + a.x + c.x + bb.x;
    float v1 = r.y + a.y + c.y + bb.y;
    float v2 = r.z + a.z + c.z + bb.z;
    float v3 = r.w + a.w + c.w + bb.w;

    __shared__ float r1[256], r2[256];
    r1[i] = v0 + v1 + v2 + v3;
    r2[i] = v0 * v0 + v1 * v1 + v2 * v2 + v3 * v3;
    __syncthreads();
    for (int st = 128; st > 0; st >>= 1) {
        if (i < st) { r1[i] += r1[i + st]; r2[i] += r2[i + st]; }
        __syncthreads();
    }
    const float mean = r1[0] * (1.f / DMOD);
    const float var = r2[0] * (1.f / DMOD) - mean * mean;
    const float rstd = rsqrtf(var + 1e-5f);
    const float4 gg = ((const float4*)g)[i];
    const float4 b2v = ((const float4*)b)[i];
    float4 o;
    o.x = (v0 - mean) * rstd * gg.x + b2v.x;
    o.y = (v1 - mean) * rstd * gg.y + b2v.y;
    o.z = (v2 - mean) * rstd * gg.z + b2v.z;
    o.w = (v3 - mean) * rstd * gg.w + b2v.w;
    ((float4*)(y + (size_t)n * DMOD))[i] = o;
}

__global__ void addemb_k(const float* __restrict__ x, const int* __restrict__ ind,
                         const int* __restrict__ outd, const float* __restrict__ ie,
                         const float* __restrict__ oe, float* __restrict__ x2)
{
    const int n = blockIdx.x;
    const float4* xr = (const float4*)(x + (size_t)n * DMOD);
    const float4* ir = (const float4*)(ie + (size_t)ind[n] * DMOD);
    const float4* orr = (const float4*)(oe + (size_t)outd[n] * DMOD);
    const int i = threadIdx.x;
    float4 a = xr[i], b = ir[i], c = orr[i];
    a.x += b.x + c.x; a.y += b.y + c.y; a.z += b.z + c.z; a.w += b.w + c.w;
    ((float4*)(x2 + (size_t)n * DMOD))[i] = a;
}

__global__ void etw_k(const float* __restrict__ re, const float* __restrict__ rw,
                      float* __restrict__ etw)
{
    const int t = threadIdx.x;
    float s = 0.f;
    for (int j = 0; j < DKH; j++) s += re[t * DKH + j] * rw[t * DKH + j];
    etw[t] = s * SCALE;
}

// bias2d packed half2: thread i computes elements 2i, 2i+1
__global__ void bias2d_k(const int* __restrict__ dist, const int4* __restrict__ pet,
                         const float4* __restrict__ paw, const float* __restrict__ plen,
                         const float* __restrict__ etw, uint32_t* __restrict__ out)
{
    const size_t i = (size_t)blockIdx.x * blockDim.x + threadIdx.x;
    float b[2];
#pragma unroll
    for (int u = 0; u < 2; u++) {
        const size_t e_i = 2 * i + u;
        const int4 e = pet[e_i];
        const float4 w = paw[e_i];
        b[u] = plen[dist[e_i]] + etw[e.x] * w.x + etw[e.y] * w.y +
               etw[e.z] * w.z + etw[e.w] * w.w;
    }
    out[i] = h2(b[0], b[1]);
}

// ---------------------------------------------------------------------------
extern "C" void kernel_launch(void* const* d_in, const int* in_sizes, int n_in,
                              void* d_out, int out_size)
{
    const float* x      = (const float*)d_in[0];
    const float* lgx    = (const float*)d_in[1];
    const int* in_deg   = (const int*)d_in[2];
    const int* out_deg  = (const int*)d_in[3];
    const int* dist     = (const int*)d_in[4];
    const int* pet      = (const int*)d_in[5];
    const float* paw    = (const float*)d_in[6];
    const float* rel_e  = (const float*)d_in[7];
    const float* rel_w  = (const float*)d_in[8];
    const float* ide    = (const float*)d_in[9];
    const float* ode    = (const float*)d_in[10];
    const float* plen   = (const float*)d_in[11];
    const float* Wq = (const float*)d_in[12];  const float* bq = (const float*)d_in[13];
    const float* Wk = (const float*)d_in[14];  const float* bk = (const float*)d_in[15];
    const float* Wv = (const float*)d_in[16];  const float* bv = (const float*)d_in[17];
    const float* Wo = (const float*)d_in[18];  const float* bo = (const float*)d_in[19];
    const float* ln1g = (const float*)d_in[20]; const float* ln1b = (const float*)d_in[21];
    const float* W1 = (const float*)d_in[22];  const float* b1 = (const float*)d_in[23];
    const float* W2 = (const float*)d_in[24];  const float* b2 = (const float*)d_in[25];
    const float* ln2g = (const float*)d_in[26]; const float* ln2b = (const float*)d_in[27];
    float* out = (float*)d_out;

    float *x2, *bqkv, *qkv, *h1, *part, *etw;
    uint32_t *bias2dH, *aoH, *ffH, *Wqp, *Wop, *W1p, *W2p, *Kp, *Vp;
    cudaGetSymbolAddress((void**)&x2, g_x2);
    cudaGetSymbolAddress((void**)&bias2dH, g_bias2dH);
    cudaGetSymbolAddress((void**)&bqkv, g_bqkv);
    cudaGetSymbolAddress((void**)&qkv, g_qkv);
    cudaGetSymbolAddress((void**)&aoH, g_aoH);
    cudaGetSymbolAddress((void**)&h1, g_h1);
    cudaGetSymbolAddress((void**)&ffH, g_ffH);
    cudaGetSymbolAddress((void**)&part, g_part);
    cudaGetSymbolAddress((void**)&etw, g_etw);
    cudaGetSymbolAddress((void**)&Wqp, g_Wqp);
    cudaGetSymbolAddress((void**)&Wop, g_Wop);
    cudaGetSymbolAddress((void**)&W1p, g_W1p);
    cudaGetSymbolAddress((void**)&W2p, g_W2p);
    cudaGetSymbolAddress((void**)&Kp, g_Kp);
    cudaGetSymbolAddress((void**)&Vp, g_Vp);

    cudaFuncSetAttribute(hgemm_t<0>, cudaFuncAttributeMaxDynamicSharedMemorySize,
                         HSMEM_BYTES);
    cudaFuncSetAttribute(hgemm_t<1>, cudaFuncAttributeMaxDynamicSharedMemorySize,
                         HSMEM_BYTES);
    cudaFuncSetAttribute(flash_h, cudaFuncAttributeMaxDynamicSharedMemorySize,
                         FLASH_SMEM);

    static cudaStream_t s2 = nullptr;
    static cudaEvent_t evFork = nullptr, evJoin = nullptr;
    if (!s2) {
        cudaStreamCreateWithFlags(&s2, cudaStreamNonBlocking);
        cudaEventCreateWithFlags(&evFork, cudaEventDisableTiming);
        cudaEventCreateWithFlags(&evJoin, cudaEventDisableTiming);
    }

    const size_t ND = (size_t)NTOK * DMOD;
    const int WQW = 512 * DMOD;
    const int N3 = 3 * DMOD;

    // fork: side stream does lgx copy + etw + bias2d + late weight packs
    cudaEventRecord(evFork, 0);
    cudaStreamWaitEvent(s2, evFork, 0);
    cudaMemcpyAsync(out + ND, lgx, (size_t)NTOK * 8 * DMOD * sizeof(float),
                    cudaMemcpyDeviceToDevice, s2);
    etw_k<<<1, 64, 0, s2>>>(rel_e, rel_w, etw);
    bias2d_k<<<(NTOK * NTOK / 2) / 256, 256, 0, s2>>>(
        dist, (const int4*)pet, (const float4*)paw, plen, etw, bias2dH);
    packW_k<<<WQW / 256, 256, 0, s2>>>(Wo, Wop, DMOD, DMOD, 0);
    packW_k<<<512 * FFD / 256, 256, 0, s2>>>(W1, W1p, FFD, FFD, 0);
    packW_k<<<2048 * DMOD / 256, 256, 0, s2>>>(W2, W2p, DMOD, DMOD, 0);
    cudaEventRecord(evJoin, s2);

    // main: QKV weight packs into [512][3072], biases, addemb
    packW_k<<<WQW / 256, 256>>>(Wq, Wqp, DMOD, N3, 0);
    packW_k<<<WQW / 256, 256>>>(Wk, Wqp, DMOD, N3, DMOD);
    packW_k<<<WQW / 256, 256>>>(Wv, Wqp, DMOD, N3, 2 * DMOD);
    cudaMemcpyAsync(bqkv,            bq, DMOD * 4, cudaMemcpyDeviceToDevice);
    cudaMemcpyAsync(bqkv + DMOD,     bk, DMOD * 4, cudaMemcpyDeviceToDevice);
    cudaMemcpyAsync(bqkv + 2 * DMOD, bv, DMOD * 4, cudaMemcpyDeviceToDevice);
    addemb_k<<<NTOK, 256>>>(x, in_deg, out_deg, ide, ode, x2);

    // QKV: single fused GEMM N=3072, bias fused, column-split fp32 output
    hgemm_t<0><<<dim3(N3 / 128, 16, 1), 256, HSMEM_BYTES>>>(
        x2, Wqp, bqkv, qkv, nullptr, NTOK, N3, DMOD, ND, 0, 1, DMOD);

    // repack K,V to half2
    packKV_k<<<dim3(HEADS * 64 * NTOK / 256, 1, 2), 256>>>(qkv, Kp, Vp);

    // join: flash needs bias2dH
    cudaStreamWaitEvent(0, evJoin, 0);
    flash_h<<<dim3(1, 32, HEADS), 256, FLASH_SMEM>>>(qkv, Kp, Vp, bias2dH, aoH);

    // Wo: A = aoH (packed half2), split-K=2 -> partials; fused LN1
    hgemm_t<1><<<dim3(8, 16, 2), 256, HSMEM_BYTES>>>(
        aoH, Wop, nullptr, part, nullptr, NTOK, DMOD, DMOD, ND, 0, 2, 0);
    red_ln_k<<<NTOK, 256>>>(part, bo, x2, ln1g, ln1b, h1);

    // FFN1 (+b1, relu) -> packed half2 ffH
    hgemm_t<0><<<dim3(32, 16, 1), 256, HSMEM_BYTES>>>(
        h1, W1p, b1, nullptr, ffH, NTOK, FFD, DMOD, 0, 1, 1, 0);
    // FFN2: A = ffH (packed half2), split-K=2 -> partials; fused LN2
    hgemm_t<1><<<dim3(8, 16, 2), 256, HSMEM_BYTES>>>(
        ffH, W2p, nullptr, part, nullptr, NTOK, DMOD, FFD, ND, 0, 2, 0);
    red_ln_k<<<NTOK, 256>>>(part, b2, h1, ln2g, ln2b, out);
}

// round 16
// speedup vs baseline: 1.0166x; 1.0166x over previous
#include <cuda_runtime.h>
#include <cuda_fp16.h>
#include <cstdint>
#include <cstddef>

// ---------------------------------------------------------------------------
// Rel_Transformer_Layer: N=2048, D=1024, H=8, DK=128, L=4, FF=4096
// Round 16: R14 structure (fused QKV N=3072, fp32-A hgemm, 64-row occ-2
// flash, fused LN tails) + half2 bias2d in flash (halves its bias stream).
// ---------------------------------------------------------------------------

#define NTOK 2048
#define DMOD 1024
#define HEADS 8
#define DKH 128
#define FFD 4096
#define SCALE 0.08838834764831845f

// -------------------- scratch ------------------
__device__ float g_x2[NTOK * DMOD];
__device__ uint32_t g_bias2dH[(size_t)NTOK * NTOK / 2];
__device__ float g_bqkv[3 * DMOD];
__device__ float g_qkv[3 * NTOK * DMOD];
__device__ float g_ao[NTOK * DMOD];
__device__ float g_h1[NTOK * DMOD];
__device__ float g_ff[(size_t)NTOK * FFD];
__device__ float g_part[(size_t)2 * NTOK * DMOD];
__device__ float g_etw[64];
__device__ uint32_t g_Wqp[512 * 3 * DMOD];     // [512][3072] packed half2
__device__ uint32_t g_Wop[512 * DMOD];
__device__ uint32_t g_W1p[512 * FFD];
__device__ uint32_t g_W2p[2048 * DMOD];
__device__ uint32_t g_Kp[HEADS * 64 * NTOK];   // [h][dk/2][tok]
__device__ uint32_t g_Vp[HEADS * 1024 * DKH];  // [h][tok/2][dk]

// -------------------- helpers ------------------
__device__ __forceinline__ uint32_t h2(float a, float b) {
    __half2 h = __floats2half2_rn(a, b);
    return *(uint32_t*)&h;
}
__device__ __forceinline__ void cpasync16(uint32_t s, const void* g) {
    asm volatile("cp.async.cg.shared.global [%0], [%1], 16;" :: "r"(s), "l"(g));
}
#define COMMIT() asm volatile("cp.async.commit_group;" ::: "memory")
#define WAITG1() asm volatile("cp.async.wait_group 1;" ::: "memory")

#define MMA_F16(acc, af, bf)                                               \
    asm volatile(                                                          \
        "mma.sync.aligned.m16n8k16.row.col.f32.f16.f16.f32 "               \
        "{%0,%1,%2,%3}, {%4,%5,%6,%7}, {%8,%9}, {%0,%1,%2,%3};"            \
        : "+f"(acc[0]), "+f"(acc[1]), "+f"(acc[2]), "+f"(acc[3])           \
        : "r"(af[0]), "r"(af[1]), "r"(af[2]), "r"(af[3]),                  \
          "r"(bf[0]), "r"(bf[1]))

#define AFW1H 2048
__device__ __forceinline__ void storeA_h(
    uint32_t* AFb, const float4 A0[2], const float4 A1[2],
    int wmS, int iS, int g, int tg)
{
#pragma unroll
    for (int ks = 0; ks < 2; ks++) {
        const float* f0 = (const float*)&A0[ks];
        const float* f1 = (const float*)&A1[ks];
#pragma unroll
        for (int pp = 0; pp < 2; pp++) {
            const int kp = 2 * tg + pp;
            const int tgp = kp & 3;
            const int hk = kp >> 2;
            const uint32_t w0 = h2(f0[2 * pp], f0[2 * pp + 1]);
            const uint32_t w1 = h2(f1[2 * pp], f1[2 * pp + 1]);
            const int idx = (((wmS * 2 + ks) * 4 + iS) * 32 +
                             ((g * 4 + tgp) ^ (g & 3))) * 4 + 2 * hk;
            *(uint2*)&AFb[idx] = make_uint2(w0, w1);
        }
    }
}

// 64-row variant (R13 verified)
__device__ __forceinline__ void storeA_h64(
    uint32_t* AFb, const float4 A0, const float4 A1,
    int wmS, int iS, int par, int g, int tg)
{
    const float4 A[2] = {A0, A1};
#pragma unroll
    for (int ks = 0; ks < 2; ks++) {
        const float* f = (const float*)&A[ks];
#pragma unroll
        for (int pp = 0; pp < 2; pp++) {
            const int kp = 2 * tg + pp;
            const int tgp = kp & 3;
            const int hk = kp >> 2;
            const uint32_t w = h2(f[2 * pp], f[2 * pp + 1]);
            const int idx = (((wmS * 2 + ks) * 2 + iS) * 32 +
                             ((g * 4 + tgp) ^ (g & 3))) * 4 + 2 * hk + par;
            AFb[idx] = w;
        }
    }
}

// ==================== fp16 GEMM (R14 verified) ====================
#define HPITCH 136
#define HBBW (16 * HPITCH)
#define HSMEM_BYTES ((2 * AFW1H + 3 * HBBW) * 4)

__global__ __launch_bounds__(256, 2) void hgemm(
    const float* __restrict__ A, const uint32_t* __restrict__ Bp,
    const float* __restrict__ biasvec, float* __restrict__ C,
    int M, int N, int K, size_t sA, size_t sBp, size_t sC, size_t sBias,
    int doRelu, int nsplit, int splitCols)
{
    extern __shared__ uint32_t sm[];
    uint32_t* AF = sm;
    uint32_t* BBuf = sm + 2 * AFW1H;

    const int tid = threadIdx.x, wid = tid >> 5, lane = tid & 31;
    const int g = lane >> 2, tg = lane & 3, wm = wid >> 2, wn = wid & 3;
    const int batch = blockIdx.z / nsplit, split = blockIdx.z - batch * nsplit;
    const int Keff = K / nsplit, nIter = Keff / 32;

    const float* Ab = A + (size_t)batch * sA + (size_t)split * Keff
                        + (size_t)blockIdx.y * 128 * K;
    const uint32_t* Bb = Bp + (size_t)batch * sBp
                        + (size_t)(split * Keff / 2) * N + (size_t)blockIdx.x * 128;
    float* Cb = C + (size_t)blockIdx.z * sC;
    const float* bvv = biasvec ? biasvec + (size_t)batch * sBias : nullptr;

    const int wmS = wid >> 2, iS = wid & 3;
    const float* Ag0 = Ab + (size_t)(wid * 16 + g) * K + tg * 4;
    const float* Ag1 = Ag0 + (size_t)8 * K;

    const int bRow = tid >> 5;
    const int bCol = (tid & 31) << 2;
    const uint32_t* Bg = Bb + (size_t)bRow * N + bCol;
    const uint32_t bSh = (uint32_t)__cvta_generic_to_shared(BBuf);

    float4 A0[2], A1[2];
    A0[0] = *(const float4*)(Ag0);       A0[1] = *(const float4*)(Ag0 + 16);
    A1[0] = *(const float4*)(Ag1);       A1[1] = *(const float4*)(Ag1 + 16);
    storeA_h(AF, A0, A1, wmS, iS, g, tg);
#pragma unroll
    for (int rh = 0; rh < 16; rh += 8)
        cpasync16(bSh + (((bRow + rh) * HPITCH + bCol) << 2), Bg + (size_t)rh * N);
    COMMIT();
    A0[0] = *(const float4*)(Ag0 + 32);  A0[1] = *(const float4*)(Ag0 + 48);
    A1[0] = *(const float4*)(Ag1 + 32);  A1[1] = *(const float4*)(Ag1 + 48);
    {
        const uint32_t* Bn = Bg + (size_t)16 * N;
        const uint32_t db = bSh + (HBBW << 2);
#pragma unroll
        for (int rh = 0; rh < 16; rh += 8)
            cpasync16(db + (((bRow + rh) * HPITCH + bCol) << 2), Bn + (size_t)rh * N);
    }
    COMMIT();

    float acc[4][4][4];
#pragma unroll
    for (int i = 0; i < 4; i++)
#pragma unroll
        for (int j = 0; j < 4; j++)
#pragma unroll
            for (int r = 0; r < 4; r++) acc[i][j][r] = 0.f;

    for (int it = 0; it < nIter; it++) {
        WAITG1();
        __syncthreads();
        if (it + 2 < nIter) {
            const uint32_t* Bn = Bg + (size_t)(it + 2) * 16 * N;
            const uint32_t db = bSh + (((it + 2) % 3) * HBBW << 2);
#pragma unroll
            for (int rh = 0; rh < 16; rh += 8)
                cpasync16(db + (((bRow + rh) * HPITCH + bCol) << 2), Bn + (size_t)rh * N);
        }
        COMMIT();
        if (it + 1 < nIter)
            storeA_h(AF + ((it + 1) & 1) * AFW1H, A0, A1, wmS, iS, g, tg);
        if (it + 2 < nIter) {
            const float* An0 = Ag0 + (size_t)(it + 2) * 32;
            const float* An1 = Ag1 + (size_t)(it + 2) * 32;
            A0[0] = *(const float4*)(An0);  A0[1] = *(const float4*)(An0 + 16);
            A1[0] = *(const float4*)(An1);  A1[1] = *(const float4*)(An1 + 16);
        }
        const uint32_t* AFr = AF + (it & 1) * AFW1H;
        const uint32_t* Bs = BBuf + (it % 3) * HBBW;
#pragma unroll
        for (int ks = 0; ks < 2; ks++) {
            uint32_t af[4][4], bf[4][2];
#pragma unroll
            for (int i = 0; i < 4; i++) {
                const uint4 qd = *(const uint4*)
                    &AFr[(((wm * 2 + ks) * 4 + i) * 32 + (lane ^ (g & 3))) * 4];
                af[i][0] = qd.x; af[i][1] = qd.y; af[i][2] = qd.z; af[i][3] = qd.w;
            }
            const int kl = ks * 8 + tg;
#pragma unroll
            for (int j = 0; j < 4; j++) {
                const int c0 = wn * 32 + j * 8 + g;
                bf[j][0] = Bs[kl * HPITCH + c0];
                bf[j][1] = Bs[(kl + 4) * HPITCH + c0];
            }
#pragma unroll
            for (int i = 0; i < 4; i++)
#pragma unroll
                for (int j = 0; j < 4; j++) MMA_F16(acc[i][j], af[i], bf[j]);
        }
        __syncthreads();
    }

#pragma unroll
    for (int i = 0; i < 4; i++) {
        const int row = blockIdx.y * 128 + wm * 64 + i * 16 + g;
#pragma unroll
        for (int j = 0; j < 4; j++) {
            const int col = blockIdx.x * 128 + wn * 32 + j * 8 + 2 * tg;
            float v0 = acc[i][j][0], v1 = acc[i][j][1];
            float v2 = acc[i][j][2], v3 = acc[i][j][3];
            if (bvv) {
                v0 += bvv[col]; v1 += bvv[col + 1];
                v2 += bvv[col]; v3 += bvv[col + 1];
            }
            if (doRelu) {
                v0 = fmaxf(v0, 0.f); v1 = fmaxf(v1, 0.f);
                v2 = fmaxf(v2, 0.f); v3 = fmaxf(v3, 0.f);
            }
            float* Cw;
            int pitch;
            if (splitCols) {
                const int cb = col / splitCols;
                Cw = C + (size_t)cb * sC + (size_t)row * splitCols
                       + (col - cb * splitCols);
                pitch = splitCols;
            } else {
                Cw = Cb + (size_t)row * N + col;
                pitch = N;
            }
            *(float2*)(Cw) = make_float2(v0, v1);
            *(float2*)(Cw + (size_t)8 * pitch) = make_float2(v2, v3);
        }
    }
}

// ==================== fp16 flash, 64-row blocks, occ 2, half2 bias =========
#define FBBW (32 * HPITCH)
#define PSP 68
#define F6_BB  4096
#define F6_PS  (F6_BB + 3 * FBBW)
#define F6_RED (F6_PS + 64 * PSP)
#define FLASH_SMEM ((F6_RED + 512) * 4)

__global__ __launch_bounds__(256, 2) void flash_h(
    const float* __restrict__ Q, const uint32_t* __restrict__ Kp,
    const uint32_t* __restrict__ Vp, const uint32_t* __restrict__ bias2dH,
    float* __restrict__ O)
{
    extern __shared__ uint32_t sm[];
    uint32_t* AFQ = sm;
    uint32_t* BBuf = sm + F6_BB;
    uint32_t* Ps = sm + F6_PS;
    float* redM = (float*)(sm + F6_RED);
    float* redS = redM + 256;

    const int tid = threadIdx.x, wid = tid >> 5, lane = tid & 31;
    const int g = lane >> 2, tg = lane & 3, wm = wid >> 2, wn = wid & 3;
    const int h = blockIdx.z, by = blockIdx.y;

    const float* Qh = Q + (size_t)h * 256 * DMOD;
    const uint32_t* Kh = Kp + (size_t)h * 64 * NTOK;
    const uint32_t* Vh = Vp + (size_t)h * 1024 * DKH;

    const int bRow = tid >> 5, bCol = (tid & 31) << 2;
    const uint32_t bSh = (uint32_t)__cvta_generic_to_shared(BBuf);
    auto issue_body = [&](int qq) {
        const int t = qq >> 2, ph = qq & 3;
        const uint32_t* src;
        int stride;
        if (ph < 2) { src = Kh + (size_t)(ph * 32 + bRow) * NTOK + t * 128 + bCol; stride = NTOK; }
        else        { src = Vh + (size_t)(t * 64 + (ph - 2) * 32 + bRow) * DKH + bCol; stride = DKH; }
        const uint32_t db = bSh + ((qq % 3) * FBBW << 2);
#pragma unroll
        for (int rh = 0; rh < 32; rh += 8)
            cpasync16(db + (((bRow + rh) * HPITCH + bCol) << 2), src + (size_t)rh * stride);
    };
    issue_body(0); COMMIT();
    issue_body(1); COMMIT();

    {
        const int blk = wid >> 1, par = wid & 1;
        const int wmS = blk >> 1, iS = blk & 1;
        const float* Qg = Qh + (size_t)(by * 64 + wid * 8 + g) * DKH + tg * 4;
#pragma unroll
        for (int c = 0; c < 4; c++) {
            const float4 A0 = *(const float4*)(Qg + c * 32);
            const float4 A1 = *(const float4*)(Qg + c * 32 + 16);
            storeA_h64(AFQ + c * 1024, A0, A1, wmS, iS, par, g, tg);
        }
    }

    float m4[4], l4[4], oacc[2][4][4];
#pragma unroll
    for (int s = 0; s < 4; s++) { m4[s] = -1e30f; l4[s] = 0.f; }
#pragma unroll
    for (int i = 0; i < 2; i++)
#pragma unroll
        for (int j = 0; j < 4; j++)
#pragma unroll
            for (int r = 0; r < 4; r++) oacc[i][j][r] = 0.f;

    int q = 0;
    for (int t = 0; t < 16; t++) {
        float sacc[2][4][4];
#pragma unroll
        for (int i = 0; i < 2; i++)
#pragma unroll
            for (int j = 0; j < 4; j++)
#pragma unroll
                for (int r = 0; r < 4; r++) sacc[i][j][r] = 0.f;

        for (int c = 0; c < 2; c++, q++) {
            WAITG1();
            __syncthreads();
            if (q + 2 < 64) issue_body(q + 2);
            COMMIT();
            const uint32_t* Bs = BBuf + (q % 3) * FBBW;
#pragma unroll
            for (int ks4 = 0; ks4 < 4; ks4++) {
                const uint32_t* AFr = AFQ + (c * 2 + (ks4 >> 1)) * 1024;
                const int ks = ks4 & 1;
                uint32_t af[2][4], bf[4][2];
#pragma unroll
                for (int i = 0; i < 2; i++) {
                    const uint4 qd = *(const uint4*)
                        &AFr[(((wm * 2 + ks) * 2 + i) * 32 + (lane ^ (g & 3))) * 4];
                    af[i][0] = qd.x; af[i][1] = qd.y; af[i][2] = qd.z; af[i][3] = qd.w;
                }
                const int kl = ks4 * 8 + tg;
#pragma unroll
                for (int j = 0; j < 4; j++) {
                    const int c0 = wn * 32 + j * 8 + g;
                    bf[j][0] = Bs[kl * HPITCH + c0];
                    bf[j][1] = Bs[(kl + 4) * HPITCH + c0];
                }
#pragma unroll
                for (int i = 0; i < 2; i++)
#pragma unroll
                    for (int j = 0; j < 4; j++) MMA_F16(sacc[i][j], af[i], bf[j]);
            }
            __syncthreads();
        }

        // scale + bias (half2 packed bias)
#pragma unroll
        for (int i = 0; i < 2; i++) {
            const int rg = by * 64 + wm * 32 + i * 16 + g;
#pragma unroll
            for (int j = 0; j < 4; j++) {
                const int cg = t * 128 + wn * 32 + j * 8 + 2 * tg;
                const uint32_t bw0 = bias2dH[((size_t)rg * NTOK + cg) >> 1];
                const uint32_t bw1 = bias2dH[((size_t)(rg + 8) * NTOK + cg) >> 1];
                const float2 b0 = __half22float2(*(const __half2*)&bw0);
                const float2 b1 = __half22float2(*(const __half2*)&bw1);
                sacc[i][j][0] = sacc[i][j][0] * SCALE + b0.x;
                sacc[i][j][1] = sacc[i][j][1] * SCALE + b0.y;
                sacc[i][j][2] = sacc[i][j][2] * SCALE + b1.x;
                sacc[i][j][3] = sacc[i][j][3] * SCALE + b1.y;
            }
        }

        float pm[4];
#pragma unroll
        for (int i = 0; i < 2; i++)
#pragma unroll
            for (int h2i = 0; h2i < 2; h2i++) {
                float v = -1e30f;
#pragma unroll
                for (int j = 0; j < 4; j++)
                    v = fmaxf(v, fmaxf(sacc[i][j][2 * h2i], sacc[i][j][2 * h2i + 1]));
                pm[i * 2 + h2i] = v;
            }
#pragma unroll
        for (int s = 0; s < 4; s++) {
            pm[s] = fmaxf(pm[s], __shfl_xor_sync(~0u, pm[s], 1));
            pm[s] = fmaxf(pm[s], __shfl_xor_sync(~0u, pm[s], 2));
        }
#pragma unroll
        for (int s = 0; s < 4; s++) {
            const int row = wm * 32 + (s >> 1) * 16 + (s & 1) * 8 + g;
            if (tg == 0) redM[row * 4 + wn] = pm[s];
        }
        __syncthreads();

        float alpha[4], nm[4];
#pragma unroll
        for (int s = 0; s < 4; s++) {
            const int row = wm * 32 + (s >> 1) * 16 + (s & 1) * 8 + g;
            float tm = fmaxf(fmaxf(redM[row * 4], redM[row * 4 + 1]),
                             fmaxf(redM[row * 4 + 2], redM[row * 4 + 3]));
            nm[s] = fmaxf(m4[s], tm);
            alpha[s] = __expf(m4[s] - nm[s]);
            m4[s] = nm[s];
        }

        float ps[4];
#pragma unroll
        for (int s = 0; s < 4; s++) ps[s] = 0.f;
#pragma unroll
        for (int i = 0; i < 2; i++)
#pragma unroll
            for (int h2i = 0; h2i < 2; h2i++) {
                const int row = wm * 32 + i * 16 + h2i * 8 + g;
#pragma unroll
                for (int j = 0; j < 4; j++) {
                    const int cw = wn * 16 + j * 4 + tg;
                    float p0 = __expf(sacc[i][j][2 * h2i] - nm[i * 2 + h2i]);
                    float p1 = __expf(sacc[i][j][2 * h2i + 1] - nm[i * 2 + h2i]);
                    ps[i * 2 + h2i] += p0 + p1;
                    Ps[row * PSP + cw] = h2(p0, p1);
                }
            }
#pragma unroll
        for (int s = 0; s < 4; s++) {
            ps[s] += __shfl_xor_sync(~0u, ps[s], 1);
            ps[s] += __shfl_xor_sync(~0u, ps[s], 2);
            const int row = wm * 32 + (s >> 1) * 16 + (s & 1) * 8 + g;
            if (tg == 0) redS[row * 4 + wn] = ps[s];
        }
        __syncthreads();
#pragma unroll
        for (int s = 0; s < 4; s++) {
            const int row = wm * 32 + (s >> 1) * 16 + (s & 1) * 8 + g;
            const float ts = redS[row * 4] + redS[row * 4 + 1] +
                             redS[row * 4 + 2] + redS[row * 4 + 3];
            l4[s] = alpha[s] * l4[s] + ts;
        }
#pragma unroll
        for (int i = 0; i < 2; i++)
#pragma unroll
            for (int j = 0; j < 4; j++) {
                oacc[i][j][0] *= alpha[i * 2];
                oacc[i][j][1] *= alpha[i * 2];
                oacc[i][j][2] *= alpha[i * 2 + 1];
                oacc[i][j][3] *= alpha[i * 2 + 1];
            }

        for (int c = 0; c < 2; c++, q++) {
            WAITG1();
            __syncthreads();
            if (q + 2 < 64) issue_body(q + 2);
            COMMIT();
            const uint32_t* Bs = BBuf + (q % 3) * FBBW;
#pragma unroll
            for (int ks4 = 0; ks4 < 4; ks4++) {
                uint32_t af[2][4], bf[4][2];
                const int kk = c * 32 + ks4 * 8 + tg;
#pragma unroll
                for (int i = 0; i < 2; i++) {
                    const int r0 = wm * 32 + i * 16 + g;
                    af[i][0] = Ps[r0 * PSP + kk];
                    af[i][1] = Ps[(r0 + 8) * PSP + kk];
                    af[i][2] = Ps[r0 * PSP + kk + 4];
                    af[i][3] = Ps[(r0 + 8) * PSP + kk + 4];
                }
                const int kl = ks4 * 8 + tg;
#pragma unroll
                for (int j = 0; j < 4; j++) {
                    const int c0 = wn * 32 + j * 8 + g;
                    bf[j][0] = Bs[kl * HPITCH + c0];
                    bf[j][1] = Bs[(kl + 4) * HPITCH + c0];
                }
#pragma unroll
                for (int i = 0; i < 2; i++)
#pragma unroll
                    for (int j = 0; j < 4; j++) MMA_F16(oacc[i][j], af[i], bf[j]);
            }
            __syncthreads();
        }
    }

    float* Oh = O + (size_t)h * 256 * DMOD;
#pragma unroll
    for (int i = 0; i < 2; i++) {
        const int row = by * 64 + wm * 32 + i * 16 + g;
        const float inv0 = 1.f / l4[i * 2];
        const float inv1 = 1.f / l4[i * 2 + 1];
#pragma unroll
        for (int j = 0; j < 4; j++) {
            const int col = wn * 32 + j * 8 + 2 * tg;
            *(float2*)(Oh + (size_t)row * DKH + col) =
                make_float2(oacc[i][j][0] * inv0, oacc[i][j][1] * inv0);
            *(float2*)(Oh + (size_t)(row + 8) * DKH + col) =
                make_float2(oacc[i][j][2] * inv1, oacc[i][j][3] * inv1);
        }
    }
}

// ---- weight pack: Wp[k2*NS + off + n] ----
__global__ void packW_k(const float* __restrict__ W, uint32_t* __restrict__ Wp,
                        int N, int NS, int off)
{
    const size_t i = (size_t)blockIdx.x * 256 + threadIdx.x;
    const size_t k2 = i / N, n = i - k2 * N;
    Wp[k2 * NS + off + n] = h2(W[2 * k2 * N + n], W[(2 * k2 + 1) * N + n]);
}

// ---- K/V repack ----
__global__ void packKV_k(const float* __restrict__ qkv,
                         uint32_t* __restrict__ Kp, uint32_t* __restrict__ Vp)
{
    const size_t i = (size_t)blockIdx.x * 256 + threadIdx.x;
    const size_t ND = (size_t)NTOK * DMOD;
    if (blockIdx.z == 0) {
        const int hh = (int)(i >> 17);
        const size_t r = i & 131071;
        const size_t d2 = r >> 11, tk = r & 2047;
        const float* base = qkv + ND + (size_t)hh * 256 * DMOD;
        Kp[i] = h2(base[2 * d2 * 2048 + tk], base[(2 * d2 + 1) * 2048 + tk]);
    } else {
        const int hh = (int)(i >> 17);
        const size_t r = i & 131071;
        const size_t t2 = r >> 7, d = r & 127;
        const float* base = qkv + 2 * ND + (size_t)hh * 256 * DMOD;
        Vp[i] = h2(base[2 * t2 * 128 + d], base[(2 * t2 + 1) * 128 + d]);
    }
}

// ---- fused: y = LayerNorm(resid + part0 + part1 + bias) * g + b ----
__global__ void red_ln_k(const float* __restrict__ part,
                         const float* __restrict__ bias,
                         const float* __restrict__ resid,
                         const float* __restrict__ g, const float* __restrict__ b,
                         float* __restrict__ y)
{
    const int n = blockIdx.x;
    const size_t ND = (size_t)NTOK * DMOD;
    const float4* p0 = (const float4*)(part + (size_t)n * DMOD);
    const float4* p1 = (const float4*)(part + ND + (size_t)n * DMOD);
    const float4* br = (const float4*)bias;
    const float4* rr = (const float4*)(resid + (size_t)n * DMOD);
    const int i = threadIdx.x;
    float4 a = p0[i], c = p1[i], bb = br[i], r = rr[i];
    float v0 = r.x + a.x + c.x + bb.x;
    float v1 = r.y + a.y + c.y + bb.y;
    float v2 = r.z + a.z + c.z + bb.z;
    float v3 = r.w + a.w + c.w + bb.w;

    __shared__ float r1[256], r2[256];
    r1[i] = v0 + v1 + v2 + v3;
    r2[i] = v0 * v0 + v1 * v1 + v2 * v2 + v3 * v3;
    __syncthreads();
    for (int st = 128; st > 0; st >>= 1) {
        if (i < st) { r1[i] += r1[i + st]; r2[i] += r2[i + st]; }
        __syncthreads();
    }
    const float mean = r1[0] * (1.f / DMOD);
    const float var = r2[0] * (1.f / DMOD) - mean * mean;
    const float rstd = rsqrtf(var + 1e-5f);
    const float4 gg = ((const float4*)g)[i];
    const float4 b2v = ((const float4*)b)[i];
    float4 o;
    o.x = (v0 - mean) * rstd * gg.x + b2v.x;
    o.y = (v1 - mean) * rstd * gg.y + b2v.y;
    o.z = (v2 - mean) * rstd * gg.z + b2v.z;
    o.w = (v3 - mean) * rstd * gg.w + b2v.w;
    ((float4*)(y + (size_t)n * DMOD))[i] = o;
}

__global__ void addemb_k(const float* __restrict__ x, const int* __restrict__ ind,
                         const int* __restrict__ outd, const float* __restrict__ ie,
                         const float* __restrict__ oe, float* __restrict__ x2)
{
    const int n = blockIdx.x;
    const float4* xr = (const float4*)(x + (size_t)n * DMOD);
    const float4* ir = (const float4*)(ie + (size_t)ind[n] * DMOD);
    const float4* orr = (const float4*)(oe + (size_t)outd[n] * DMOD);
    const int i = threadIdx.x;
    float4 a = xr[i], b = ir[i], c = orr[i];
    a.x += b.x + c.x; a.y += b.y + c.y; a.z += b.z + c.z; a.w += b.w + c.w;
    ((float4*)(x2 + (size_t)n * DMOD))[i] = a;
}

__global__ void etw_k(const float* __restrict__ re, const float* __restrict__ rw,
                      float* __restrict__ etw)
{
    const int t = threadIdx.x;
    float s = 0.f;
    for (int j = 0; j < DKH; j++) s += re[t * DKH + j] * rw[t * DKH + j];
    etw[t] = s * SCALE;
}

// bias2d packed half2: thread i computes elements 2i, 2i+1
__global__ void bias2d_k(const int* __restrict__ dist, const int4* __restrict__ pet,
                         const float4* __restrict__ paw, const float* __restrict__ plen,
                         const float* __restrict__ etw, uint32_t* __restrict__ out)
{
    const size_t i = (size_t)blockIdx.x * blockDim.x + threadIdx.x;
    float b[2];
#pragma unroll
    for (int u = 0; u < 2; u++) {
        const size_t e_i = 2 * i + u;
        const int4 e = pet[e_i];
        const float4 w = paw[e_i];
        b[u] = plen[dist[e_i]] + etw[e.x] * w.x + etw[e.y] * w.y +
               etw[e.z] * w.z + etw[e.w] * w.w;
    }
    out[i] = h2(b[0], b[1]);
}

// ---------------------------------------------------------------------------
extern "C" void kernel_launch(void* const* d_in, const int* in_sizes, int n_in,
                              void* d_out, int out_size)
{
    const float* x      = (const float*)d_in[0];
    const float* lgx    = (const float*)d_in[1];
    const int* in_deg   = (const int*)d_in[2];
    const int* out_deg  = (const int*)d_in[3];
    const int* dist     = (const int*)d_in[4];
    const int* pet      = (const int*)d_in[5];
    const float* paw    = (const float*)d_in[6];
    const float* rel_e  = (const float*)d_in[7];
    const float* rel_w  = (const float*)d_in[8];
    const float* ide    = (const float*)d_in[9];
    const float* ode    = (const float*)d_in[10];
    const float* plen   = (const float*)d_in[11];
    const float* Wq = (const float*)d_in[12];  const float* bq = (const float*)d_in[13];
    const float* Wk = (const float*)d_in[14];  const float* bk = (const float*)d_in[15];
    const float* Wv = (const float*)d_in[16];  const float* bv = (const float*)d_in[17];
    const float* Wo = (const float*)d_in[18];  const float* bo = (const float*)d_in[19];
    const float* ln1g = (const float*)d_in[20]; const float* ln1b = (const float*)d_in[21];
    const float* W1 = (const float*)d_in[22];  const float* b1 = (const float*)d_in[23];
    const float* W2 = (const float*)d_in[24];  const float* b2 = (const float*)d_in[25];
    const float* ln2g = (const float*)d_in[26]; const float* ln2b = (const float*)d_in[27];
    float* out = (float*)d_out;

    float *x2, *bqkv, *qkv, *ao, *h1, *ff, *part, *etw;
    uint32_t *bias2dH, *Wqp, *Wop, *W1p, *W2p, *Kp, *Vp;
    cudaGetSymbolAddress((void**)&x2, g_x2);
    cudaGetSymbolAddress((void**)&bias2dH, g_bias2dH);
    cudaGetSymbolAddress((void**)&bqkv, g_bqkv);
    cudaGetSymbolAddress((void**)&qkv, g_qkv);
    cudaGetSymbolAddress((void**)&ao, g_ao);
    cudaGetSymbolAddress((void**)&h1, g_h1);
    cudaGetSymbolAddress((void**)&ff, g_ff);
    cudaGetSymbolAddress((void**)&part, g_part);
    cudaGetSymbolAddress((void**)&etw, g_etw);
    cudaGetSymbolAddress((void**)&Wqp, g_Wqp);
    cudaGetSymbolAddress((void**)&Wop, g_Wop);
    cudaGetSymbolAddress((void**)&W1p, g_W1p);
    cudaGetSymbolAddress((void**)&W2p, g_W2p);
    cudaGetSymbolAddress((void**)&Kp, g_Kp);
    cudaGetSymbolAddress((void**)&Vp, g_Vp);

    cudaFuncSetAttribute(hgemm, cudaFuncAttributeMaxDynamicSharedMemorySize,
                         HSMEM_BYTES);
    cudaFuncSetAttribute(flash_h, cudaFuncAttributeMaxDynamicSharedMemorySize,
                         FLASH_SMEM);

    static cudaStream_t s2 = nullptr;
    static cudaEvent_t evFork = nullptr, evJoin = nullptr;
    if (!s2) {
        cudaStreamCreateWithFlags(&s2, cudaStreamNonBlocking);
        cudaEventCreateWithFlags(&evFork, cudaEventDisableTiming);
        cudaEventCreateWithFlags(&evJoin, cudaEventDisableTiming);
    }

    const size_t ND = (size_t)NTOK * DMOD;
    const int WQW = 512 * DMOD;
    const int N3 = 3 * DMOD;

    // fork: side stream does lgx copy + etw + bias2d + late weight packs
    cudaEventRecord(evFork, 0);
    cudaStreamWaitEvent(s2, evFork, 0);
    cudaMemcpyAsync(out + ND, lgx, (size_t)NTOK * 8 * DMOD * sizeof(float),
                    cudaMemcpyDeviceToDevice, s2);
    etw_k<<<1, 64, 0, s2>>>(rel_e, rel_w, etw);
    bias2d_k<<<(NTOK * NTOK / 2) / 256, 256, 0, s2>>>(
        dist, (const int4*)pet, (const float4*)paw, plen, etw, bias2dH);
    packW_k<<<WQW / 256, 256, 0, s2>>>(Wo, Wop, DMOD, DMOD, 0);
    packW_k<<<512 * FFD / 256, 256, 0, s2>>>(W1, W1p, FFD, FFD, 0);
    packW_k<<<2048 * DMOD / 256, 256, 0, s2>>>(W2, W2p, DMOD, DMOD, 0);
    cudaEventRecord(evJoin, s2);

    // main: QKV weight packs into [512][3072], biases, addemb
    packW_k<<<WQW / 256, 256>>>(Wq, Wqp, DMOD, N3, 0);
    packW_k<<<WQW / 256, 256>>>(Wk, Wqp, DMOD, N3, DMOD);
    packW_k<<<WQW / 256, 256>>>(Wv, Wqp, DMOD, N3, 2 * DMOD);
    cudaMemcpyAsync(bqkv,            bq, DMOD * 4, cudaMemcpyDeviceToDevice);
    cudaMemcpyAsync(bqkv + DMOD,     bk, DMOD * 4, cudaMemcpyDeviceToDevice);
    cudaMemcpyAsync(bqkv + 2 * DMOD, bv, DMOD * 4, cudaMemcpyDeviceToDevice);
    addemb_k<<<NTOK, 256>>>(x, in_deg, out_deg, ide, ode, x2);

    // QKV: single fused GEMM N=3072, bias fused, column-split output
    hgemm<<<dim3(N3 / 128, 16, 1), 256, HSMEM_BYTES>>>(
        x2, Wqp, bqkv, qkv, NTOK, N3, DMOD, 0, 0, ND, 0, 0, 1, DMOD);

    // repack K,V to half2
    packKV_k<<<dim3(HEADS * 64 * NTOK / 256, 1, 2), 256>>>(qkv, Kp, Vp);

    // join: flash needs bias2dH
    cudaStreamWaitEvent(0, evJoin, 0);
    flash_h<<<dim3(1, 32, HEADS), 256, FLASH_SMEM>>>(qkv, Kp, Vp, bias2dH, ao);

    // Wo: split-K=2 -> partials; fused reduce+bo+residual(x2)+LN1 -> h1
    hgemm<<<dim3(8, 16, 2), 256, HSMEM_BYTES>>>(
        ao, Wop, nullptr, part, NTOK, DMOD, DMOD, 0, 0, ND, 0, 0, 2, 0);
    red_ln_k<<<NTOK, 256>>>(part, bo, x2, ln1g, ln1b, h1);

    // FFN1 (+b1, relu)
    hgemm<<<dim3(32, 16, 1), 256, HSMEM_BYTES>>>(
        h1, W1p, b1, ff, NTOK, FFD, DMOD, 0, 0, 0, FFD, 1, 1, 0);
    // FFN2: split-K=2 -> partials; fused reduce+b2+residual(h1)+LN2 -> out
    hgemm<<<dim3(8, 16, 2), 256, HSMEM_BYTES>>>(
        ff, W2p, nullptr, part, NTOK, DMOD, FFD, 0, 0, ND, 0, 0, 2, 0);
    red_ln_k<<<NTOK, 256>>>(part, b2, h1, ln2g, ln2b, out);
}